// round 9
// baseline (speedup 1.0000x reference)
#include <cuda_runtime.h>
#include <cstdint>

// Problem constants (fixed for this problem instance)
#define RR 20000   // reviews
#define SS 64      // words per review
#define DD 128     // embedding dim
#define KK 32      // aspects
#define BB 2048    // batch
#define LL 20480   // history length (both user and item)
#define PER (LL / BB)   // 10: exact entries per segment (seg = arange(L)//(L/B))

#define GRID_REVIEW 592   // 4 blocks/SM x 148 SMs

// ---------------- device scratch (no allocation allowed) ----------------
__device__ float g_v[RR * DD];    // v[r] = M_w @ y[r]
__device__ float g_rs[RR * DD];   // per-review aspect embedding r_s

// ---- packed fp32x2 helpers (FFMA2: 2x fp32 issue rate on sm_103a) ----
#define FMA2(acc, a, b) \
    asm("fma.rn.f32x2 %0, %1, %2, %0;" : "+l"(acc) : "l"(a), "l"(b))
#define PACK2(dst, xu) \
    asm("mov.b64 %0, {%1, %1};" : "=l"(dst) : "r"(xu))
#define UNPACK2(lo, hi, src) \
    asm("mov.b64 {%0, %1}, %2;" : "=r"(lo), "=r"(hi) : "l"(src))

// ================= kernel 1: v[r,d] = sum_e M_w[d,e] * y[r,e] =================
// Occupancy-first layout: 625 blocks x 32 reviews. Thread tile = 2 reviews x
// 8 d (2 float4 chunks at d = 4*dg + 64*j) -> 8 ull accumulators = 16 regs,
// ~46 regs total, 4 blocks/SM resident (32 warps: LDS->FFMA2 latency hidden).
__global__ void __launch_bounds__(256, 4) vprep_kernel(
    const float* __restrict__ Mw,    // [D,D] row-major: Mw[d*DD+e]
    const float* __restrict__ ypos)  // [R,D]
{
    __shared__ float mw_sh[64 * 132];   // [e_local][d], padded row stride 132

    const int t  = threadIdx.x;
    const int dg = t & 15;       // ulonglong2 chunk within row; d = 4*dg + 64*j
    const int rg = t >> 4;       // 0..15 -> 2 reviews each
    const int rbase = blockIdx.x * 32 + rg * 2;   // 625*32 = 20000 exact
    const float4* y0 = reinterpret_cast<const float4*>(ypos + (size_t)rbase * DD);
    const float4* y1 = reinterpret_cast<const float4*>(ypos + (size_t)(rbase + 1) * DD);

    unsigned long long acc[2][2][2];   // [review][j][half]
    #pragma unroll
    for (int r = 0; r < 2; ++r)
        #pragma unroll
        for (int j = 0; j < 2; ++j) { acc[r][j][0] = 0ull; acc[r][j][1] = 0ull; }

    for (int h = 0; h < 2; ++h) {           // two 64-e halves of M_w
        __syncthreads();
        for (int i = t; i < 128 * 64; i += 256) {
            int d = i >> 6, el = i & 63;
            mw_sh[el * 132 + d] = Mw[d * DD + h * 64 + el];  // coalesced LDG
        }
        __syncthreads();

        #pragma unroll 4
        for (int e4 = 0; e4 < 16; ++e4) {
            float4 a4 = y0[h * 16 + e4];
            float4 b4 = y1[h * 16 + e4];
            const float fa[4] = {a4.x, a4.y, a4.z, a4.w};
            const float fb[4] = {b4.x, b4.y, b4.z, b4.w};
            #pragma unroll
            for (int j4 = 0; j4 < 4; ++j4) {
                const int e = e4 * 4 + j4;
                const ulonglong2* mrow =
                    reinterpret_cast<const ulonglong2*>(mw_sh + e * 132);
                unsigned long long pa, pb;
                PACK2(pa, __float_as_uint(fa[j4]));
                PACK2(pb, __float_as_uint(fb[j4]));
                #pragma unroll
                for (int j = 0; j < 2; ++j) {
                    ulonglong2 m = mrow[dg + 16 * j];   // 16 distinct 16B: 2-phase LDS
                    FMA2(acc[0][j][0], m.x, pa);
                    FMA2(acc[0][j][1], m.y, pa);
                    FMA2(acc[1][j][0], m.x, pb);
                    FMA2(acc[1][j][1], m.y, pb);
                }
            }
        }
    }

    #pragma unroll
    for (int r = 0; r < 2; ++r) {
        float* vrow = g_v + (size_t)(rbase + r) * DD;
        #pragma unroll
        for (int j = 0; j < 2; ++j) {
            unsigned v0, v1, v2, v3;
            UNPACK2(v0, v1, acc[r][j][0]);
            UNPACK2(v2, v3, acc[r][j][1]);
            float4 o = make_float4(__uint_as_float(v0), __uint_as_float(v1),
                                   __uint_as_float(v2), __uint_as_float(v3));
            *reinterpret_cast<float4*>(vrow + 4 * dg + 64 * j) = o;
        }
    }
}

// ================= kernel 2: persistent fused review pipeline =================
// Software pipeline across grid-stride iterations: the NEXT review's 8 wemb
// row gathers are issued right after the current z-partial frees ev[] — their
// L2 latency hides under the aspect tail (4 barriers + logits + softmaxK +
// r_s store). Tokens live in per-warp registers (shfl), no tok SMEM.
__global__ void __launch_bounds__(256, 4) review_kernel(
    const int*   __restrict__ tok,    // [R,S]
    const float* __restrict__ wemb,   // [V,D]
    const float* __restrict__ Ww,     // [D,K]
    const float* __restrict__ Wb,     // [K]
    const float* __restrict__ Tw,     // [K,D]
    const float* __restrict__ Tb)     // [D]
{
    __shared__ float wwS[KK * 129];   // [k][d], stride 129 -> bank (k+d)%32
    __shared__ float twS[KK * DD];    // [k][d]
    __shared__ float wb_sh[KK];
    __shared__ float v_sh[DD];
    __shared__ float ax_sh[SS];
    __shared__ float red[8 * DD];     // per-warp z partials
    __shared__ float z_sh[DD];
    __shared__ float lpart[8 * KK];

    const int t    = threadIdx.x;
    const int lane = t & 31;
    const int w    = t >> 5;

    // ---- one-time per-block staging ----
    for (int i = t; i < DD * KK; i += 256) {
        int d = i >> 5, k = i & 31;
        wwS[k * 129 + d] = Ww[i];
        twS[i] = Tw[i];
    }
    if (t < KK) wb_sh[t] = Wb[t];
    const float tb_reg = (t < DD) ? Tb[t] : 0.f;
    const int   part   = t >> 5;
    const float* wwrow = wwS + lane * 129 + part * 16;   // lane = logit k

    // ---- prologue: first review's tokens (per-warp regs), v, and gathers ----
    const int rfirst = blockIdx.x;
    int tokreg = 0;
    if (lane < 8) tokreg = __ldg(tok + rfirst * SS + w * 8 + lane);
    float v_pf = (t < DD) ? g_v[(size_t)rfirst * DD + t] : 0.f;

    float4 ev[8];
    #pragma unroll
    for (int i = 0; i < 8; ++i) {
        int id = __shfl_sync(0xffffffffu, tokreg, i);
        ev[i] = reinterpret_cast<const float4*>(wemb + (size_t)id * DD)[lane];
    }
    if (t < DD) v_sh[t] = v_pf;
    __syncthreads();

    for (int r = rfirst; r < RR; r += GRID_REVIEW) {
        const int rn = r + GRID_REVIEW;
        const int rc = (rn < RR) ? rn : r;

        const float4 v4 = reinterpret_cast<float4*>(v_sh)[lane];

        // ---- per-lane partial dots for this warp's 8 s-values ----
        float p[8];
        #pragma unroll
        for (int i = 0; i < 8; ++i)
            p[i] = ev[i].x * v4.x + ev[i].y * v4.y +
                   ev[i].z * v4.z + ev[i].w * v4.w;

        // ---- prefetch next review's tokens + v (regs; consumed in tail) ----
        int tokreg_n = 0;
        if (lane < 8) tokreg_n = __ldg(tok + rc * SS + w * 8 + lane);
        float v_pf_n = (t < DD) ? g_v[(size_t)rc * DD + t] : 0.f;

        // ---- folding multi-reduce: 8 dots -> 9 shfls ----
        float q[4];
        #pragma unroll
        for (int i = 0; i < 4; ++i) {
            float send = (lane & 16) ? p[i] : p[i + 4];
            float keep = (lane & 16) ? p[i + 4] : p[i];
            q[i] = keep + __shfl_xor_sync(0xffffffffu, send, 16);
        }
        float u[2];
        #pragma unroll
        for (int i = 0; i < 2; ++i) {
            float send = (lane & 8) ? q[i] : q[i + 2];
            float keep = (lane & 8) ? q[i + 2] : q[i];
            u[i] = keep + __shfl_xor_sync(0xffffffffu, send, 8);
        }
        float dx;
        {
            float send = (lane & 4) ? u[0] : u[1];
            float keep = (lane & 4) ? u[1] : u[0];
            dx = keep + __shfl_xor_sync(0xffffffffu, send, 4);
        }
        dx += __shfl_xor_sync(0xffffffffu, dx, 2);
        dx += __shfl_xor_sync(0xffffffffu, dx, 1);
        if ((lane & 3) == 0) ax_sh[w * 8 + ((lane >> 2) & 7)] = dx;
        __syncthreads();                                   // B1

        // ---- softmax over S=64 (redundant in every warp) + z partial ----
        float4 z = make_float4(0.f, 0.f, 0.f, 0.f);
        {
            float a = ax_sh[lane];
            float b = ax_sh[lane + 32];
            float m = fmaxf(a, b);
            #pragma unroll
            for (int o = 16; o; o >>= 1) m = fmaxf(m, __shfl_xor_sync(0xffffffffu, m, o));
            float ea = __expf(a - m), eb = __expf(b - m);
            float s = ea + eb;
            #pragma unroll
            for (int o = 16; o; o >>= 1) s += __shfl_xor_sync(0xffffffffu, s, o);
            float inv = __fdividef(1.f, s);
            float sel  = (w & 4) ? eb : ea;
            int   base = (w & 3) * 8;
            #pragma unroll
            for (int i = 0; i < 8; ++i) {
                float av = __shfl_sync(0xffffffffu, sel, base + i) * inv;
                z.x = fmaf(av, ev[i].x, z.x);
                z.y = fmaf(av, ev[i].y, z.y);
                z.z = fmaf(av, ev[i].z, z.z);
                z.w = fmaf(av, ev[i].w, z.w);
            }
        }

        // ---- ev[] now dead: ISSUE NEXT REVIEW'S GATHERS (latency hides
        //      under the whole aspect tail below) ----
        #pragma unroll
        for (int i = 0; i < 8; ++i) {
            int id = __shfl_sync(0xffffffffu, tokreg_n, i);
            ev[i] = reinterpret_cast<const float4*>(wemb + (size_t)id * DD)[lane];
        }

        reinterpret_cast<float4*>(red)[w * 32 + lane] = z;
        __syncthreads();                                   // B2

        // ---- z[d]: cross-warp sum of 8 partials ----
        if (t < DD) {
            float s = 0.f;
            #pragma unroll
            for (int w2 = 0; w2 < 8; ++w2)
                s += red[w2 * DD + t];
            z_sh[t] = s;
        }
        __syncthreads();                                   // B3

        // ---- aspect logits: thread (part, lane=k) -> 16-d partial ----
        {
            float a = 0.f;
            const float* zp = z_sh + part * 16;
            #pragma unroll
            for (int j = 0; j < 16; ++j)
                a = fmaf(zp[j], wwrow[j], a);
            lpart[part * KK + lane] = a;
        }
        __syncthreads();                                   // B4

        // ---- K-softmax (redundant in every warp; p in lane k's reg) ----
        float pmy;
        {
            float a = wb_sh[lane];
            #pragma unroll
            for (int pp = 0; pp < 8; ++pp) a += lpart[pp * KK + lane];
            float m = a;
            #pragma unroll
            for (int o = 16; o; o >>= 1) m = fmaxf(m, __shfl_xor_sync(0xffffffffu, m, o));
            float e = __expf(a - m);
            float s = e;
            #pragma unroll
            for (int o = 16; o; o >>= 1) s += __shfl_xor_sync(0xffffffffu, s, o);
            pmy = e * __fdividef(1.f, s);
        }

        // ---- r_s[d] = Tb[d] + sum_k p[k] * Tw[k][d] (p via shfl) ----
        if (t < DD) {
            float a = tb_reg;
            #pragma unroll
            for (int k = 0; k < KK; ++k)
                a = fmaf(__shfl_sync(0xffffffffu, pmy, k), twS[k * DD + t], a);
            g_rs[(size_t)r * DD + t] = a;
        }

        // ---- stage next v into SMEM; rotate token regs ----
        if (t < DD) v_sh[t] = v_pf_n;
        tokreg = tokreg_n;
        __syncthreads();   // B5: protects ax_sh/red/lpart/v_sh for next iter
    }
}

// ================= kernel 3: fused segment-mean + prediction =================
// Segments are exactly PER=10 contiguous entries (seg = arange(L)//10): bounds
// are arithmetic, all 10 idx loads and all 10 row loads issued independently
// (serial depth 2 rounds instead of 10).
__global__ void __launch_bounds__(256) final_kernel(
    const int*   __restrict__ user, const int* __restrict__ item,
    const int*   __restrict__ uidx, const int* __restrict__ iidx,
    const float* __restrict__ uemb, const float* __restrict__ iemb,
    const float* __restrict__ avg,  float* __restrict__ out)
{
    __shared__ float sh[256];
    __shared__ float red[4];

    const int b    = blockIdx.x;
    const int t    = threadIdx.x;
    const int side = t >> 7;          // 0 = user, 1 = item
    const int d    = t & 127;

    // hoist embedding loads (overlap with gather)
    float uf = 0.f, itf = 0.f;
    if (t < DD) {
        uf  = uemb[(size_t)user[b] * DD + t];
        itf = iemb[(size_t)item[b] * DD + t];
    }

    const int* idxp = side ? iidx : uidx;
    const int  base = b * PER;

    int ids[PER];
    #pragma unroll
    for (int j = 0; j < PER; ++j)
        ids[j] = __ldg(idxp + base + j);      // PER independent LDG

    float sum = 0.f;
    #pragma unroll
    for (int j = 0; j < PER; ++j)
        sum += g_rs[(size_t)ids[j] * DD + d]; // PER independent LDG

    sh[t] = sum * (1.0f / (float)PER);
    __syncthreads();

    if (t < DD) {
        float p = sh[t] * sh[t + 128] + uf * itf;
        #pragma unroll
        for (int o = 16; o; o >>= 1) p += __shfl_xor_sync(0xffffffffu, p, o);
        if ((t & 31) == 0) red[t >> 5] = p;
    }
    __syncthreads();
    if (t == 0) out[b] = red[0] + red[1] + red[2] + red[3] + avg[0];
}

// ---------------- launch ----------------
extern "C" void kernel_launch(void* const* d_in, const int* in_sizes, int n_in,
                              void* d_out, int out_size)
{
    const int*   user = (const int*)  d_in[0];
    const int*   item = (const int*)  d_in[1];
    const int*   hrev = (const int*)  d_in[2];
    const float* ypos = (const float*)d_in[3];
    const int*   uidx = (const int*)  d_in[4];
    const int*   iidx = (const int*)  d_in[6];
    const float* wemb = (const float*)d_in[8];
    const float* Mw   = (const float*)d_in[9];
    // d_in[10] = M_b: constant shift over s -> cancels in softmax, unused
    const float* Ww   = (const float*)d_in[11];
    const float* Wb   = (const float*)d_in[12];
    const float* Tw   = (const float*)d_in[13];
    const float* Tb   = (const float*)d_in[14];
    const float* uemb = (const float*)d_in[15];
    const float* iemb = (const float*)d_in[16];
    const float* avg  = (const float*)d_in[17];
    float* out = (float*)d_out;

    vprep_kernel <<<RR / 32, 256>>>(Mw, ypos);     // 625 blocks x 32 reviews
    review_kernel<<<GRID_REVIEW, 256>>>(hrev, wemb, Ww, Wb, Tw, Tb);
    final_kernel <<<BB, 256>>>(user, item, uidx, iidx, uemb, iemb, avg, out);
}

// round 10
// speedup vs baseline: 1.1463x; 1.1463x over previous
#include <cuda_runtime.h>
#include <cstdint>

// Problem constants (fixed for this problem instance)
#define RR 20000   // reviews
#define SS 64      // words per review
#define DD 128     // embedding dim
#define KK 32      // aspects
#define BB 2048    // batch
#define LL 20480   // history length (both user and item)
#define PER (LL / BB)   // 10: exact entries per segment (seg = arange(L)//(L/B))

#define GRID_REVIEW 592   // 4 blocks/SM x 148 SMs

// ---------------- device scratch (no allocation allowed) ----------------
__device__ float g_v[RR * DD];    // v[r] = M_w @ y[r]
__device__ float g_rs[RR * DD];   // per-review aspect embedding r_s

// ---- packed fp32x2 helpers (FFMA2: 2x fp32 issue rate on sm_103a) ----
#define FMA2(acc, a, b) \
    asm("fma.rn.f32x2 %0, %1, %2, %0;" : "+l"(acc) : "l"(a), "l"(b))
#define PACK2(dst, xu) \
    asm("mov.b64 %0, {%1, %1};" : "=l"(dst) : "r"(xu))
#define UNPACK2(lo, hi, src) \
    asm("mov.b64 {%0, %1}, %2;" : "=r"(lo), "=r"(hi) : "l"(src))

// ================= kernel 1: v[r,d] = sum_e M_w[d,e] * y[r,e] =================
// Reuse-4 layout: 313 blocks x 64 reviews; thread tile = 4 reviews x 8 d.
// Each LDS.128 of M_w now feeds 8 FFMA2 (vs 4): LDS traffic halved vs R9
// (328 MB chip-wide ~ 10us floor), FFMA2 floor ~9.5us -> balanced.
__global__ void __launch_bounds__(256, 3) vprep_kernel(
    const float* __restrict__ Mw,    // [D,D] row-major: Mw[d*DD+e]
    const float* __restrict__ ypos)  // [R,D]
{
    __shared__ float mw_sh[64 * 132];   // [e_local][d], padded row stride 132

    const int t  = threadIdx.x;
    const int dg = t & 15;       // ulonglong2 chunk: d = 4*dg + 64*j
    const int rg = t >> 4;       // 0..15 -> 4 reviews each
    const int rbase = blockIdx.x * 64 + rg * 4;

    const float4* yp[4];
    #pragma unroll
    for (int rv = 0; rv < 4; ++rv) {
        int rc = rbase + rv; if (rc >= RR) rc = RR - 1;
        yp[rv] = reinterpret_cast<const float4*>(ypos + (size_t)rc * DD);
    }

    unsigned long long acc[4][2][2];   // [review][j][half]
    #pragma unroll
    for (int rv = 0; rv < 4; ++rv)
        #pragma unroll
        for (int j = 0; j < 2; ++j) { acc[rv][j][0] = 0ull; acc[rv][j][1] = 0ull; }

    for (int h = 0; h < 2; ++h) {           // two 64-e halves of M_w
        __syncthreads();
        for (int i = t; i < 128 * 64; i += 256) {
            int d = i >> 6, el = i & 63;
            mw_sh[el * 132 + d] = Mw[d * DD + h * 64 + el];  // coalesced LDG
        }
        __syncthreads();

        #pragma unroll 2
        for (int e4 = 0; e4 < 16; ++e4) {
            float4 ya[4];
            #pragma unroll
            for (int rv = 0; rv < 4; ++rv) ya[rv] = yp[rv][h * 16 + e4];

            #pragma unroll
            for (int j4 = 0; j4 < 4; ++j4) {
                const int e = e4 * 4 + j4;
                const ulonglong2* mrow =
                    reinterpret_cast<const ulonglong2*>(mw_sh + e * 132);
                const ulonglong2 m0 = mrow[dg];        // 2-wavefront LDS.128
                const ulonglong2 m1 = mrow[dg + 16];
                const float ys[4] = {
                    j4 == 0 ? ya[0].x : j4 == 1 ? ya[0].y : j4 == 2 ? ya[0].z : ya[0].w,
                    j4 == 0 ? ya[1].x : j4 == 1 ? ya[1].y : j4 == 2 ? ya[1].z : ya[1].w,
                    j4 == 0 ? ya[2].x : j4 == 1 ? ya[2].y : j4 == 2 ? ya[2].z : ya[2].w,
                    j4 == 0 ? ya[3].x : j4 == 1 ? ya[3].y : j4 == 2 ? ya[3].z : ya[3].w };
                #pragma unroll
                for (int rv = 0; rv < 4; ++rv) {
                    unsigned long long pr;
                    PACK2(pr, __float_as_uint(ys[rv]));
                    FMA2(acc[rv][0][0], m0.x, pr);
                    FMA2(acc[rv][0][1], m0.y, pr);
                    FMA2(acc[rv][1][0], m1.x, pr);
                    FMA2(acc[rv][1][1], m1.y, pr);
                }
            }
        }
    }

    #pragma unroll
    for (int rv = 0; rv < 4; ++rv) {
        if (rbase + rv >= RR) break;
        float* vrow = g_v + (size_t)(rbase + rv) * DD;
        #pragma unroll
        for (int j = 0; j < 2; ++j) {
            unsigned v0, v1, v2, v3;
            UNPACK2(v0, v1, acc[rv][j][0]);
            UNPACK2(v2, v3, acc[rv][j][1]);
            float4 o = make_float4(__uint_as_float(v0), __uint_as_float(v1),
                                   __uint_as_float(v2), __uint_as_float(v3));
            *reinterpret_cast<float4*>(vrow + 4 * dg + 64 * j) = o;
        }
    }
}

// ================= kernel 2: persistent fused review pipeline =================
// Software pipeline across grid-stride iterations: the NEXT review's 8 wemb
// row gathers are issued right after the current z-partial frees ev[].
// K-softmax now runs in warp 0 only -> p_sh; r_s phase reads p via LDS
// broadcast (removes 128 warp-SHFLs/iter of MIO pressure).
__global__ void __launch_bounds__(256, 4) review_kernel(
    const int*   __restrict__ tok,    // [R,S]
    const float* __restrict__ wemb,   // [V,D]
    const float* __restrict__ Ww,     // [D,K]
    const float* __restrict__ Wb,     // [K]
    const float* __restrict__ Tw,     // [K,D]
    const float* __restrict__ Tb)     // [D]
{
    __shared__ float wwS[KK * 129];   // [k][d], stride 129 -> bank (k+d)%32
    __shared__ float twS[KK * DD];    // [k][d]
    __shared__ float wb_sh[KK];
    __shared__ float v_sh[DD];
    __shared__ float ax_sh[SS];
    __shared__ float red[8 * DD];     // per-warp z partials
    __shared__ float z_sh[DD];
    __shared__ float lpart[8 * KK];
    __shared__ float p_sh[KK];

    const int t    = threadIdx.x;
    const int lane = t & 31;
    const int w    = t >> 5;

    // ---- one-time per-block staging ----
    for (int i = t; i < DD * KK; i += 256) {
        int d = i >> 5, k = i & 31;
        wwS[k * 129 + d] = Ww[i];
        twS[i] = Tw[i];
    }
    if (t < KK) wb_sh[t] = Wb[t];
    const float tb_reg = (t < DD) ? Tb[t] : 0.f;
    const int   part   = t >> 5;
    const float* wwrow = wwS + lane * 129 + part * 16;   // lane = logit k

    // ---- prologue: first review's tokens (per-warp regs), v, and gathers ----
    const int rfirst = blockIdx.x;
    int tokreg = 0;
    if (lane < 8) tokreg = __ldg(tok + rfirst * SS + w * 8 + lane);
    float v_pf = (t < DD) ? g_v[(size_t)rfirst * DD + t] : 0.f;

    float4 ev[8];
    #pragma unroll
    for (int i = 0; i < 8; ++i) {
        int id = __shfl_sync(0xffffffffu, tokreg, i);
        ev[i] = reinterpret_cast<const float4*>(wemb + (size_t)id * DD)[lane];
    }
    if (t < DD) v_sh[t] = v_pf;
    __syncthreads();

    for (int r = rfirst; r < RR; r += GRID_REVIEW) {
        const int rn = r + GRID_REVIEW;
        const int rc = (rn < RR) ? rn : r;

        const float4 v4 = reinterpret_cast<float4*>(v_sh)[lane];

        // ---- per-lane partial dots for this warp's 8 s-values ----
        float p[8];
        #pragma unroll
        for (int i = 0; i < 8; ++i)
            p[i] = ev[i].x * v4.x + ev[i].y * v4.y +
                   ev[i].z * v4.z + ev[i].w * v4.w;

        // ---- prefetch next review's tokens + v (regs; consumed in tail) ----
        int tokreg_n = 0;
        if (lane < 8) tokreg_n = __ldg(tok + rc * SS + w * 8 + lane);
        float v_pf_n = (t < DD) ? g_v[(size_t)rc * DD + t] : 0.f;

        // ---- folding multi-reduce: 8 dots -> 9 shfls ----
        float q[4];
        #pragma unroll
        for (int i = 0; i < 4; ++i) {
            float send = (lane & 16) ? p[i] : p[i + 4];
            float keep = (lane & 16) ? p[i + 4] : p[i];
            q[i] = keep + __shfl_xor_sync(0xffffffffu, send, 16);
        }
        float u[2];
        #pragma unroll
        for (int i = 0; i < 2; ++i) {
            float send = (lane & 8) ? q[i] : q[i + 2];
            float keep = (lane & 8) ? q[i + 2] : q[i];
            u[i] = keep + __shfl_xor_sync(0xffffffffu, send, 8);
        }
        float dx;
        {
            float send = (lane & 4) ? u[0] : u[1];
            float keep = (lane & 4) ? u[1] : u[0];
            dx = keep + __shfl_xor_sync(0xffffffffu, send, 4);
        }
        dx += __shfl_xor_sync(0xffffffffu, dx, 2);
        dx += __shfl_xor_sync(0xffffffffu, dx, 1);
        if ((lane & 3) == 0) ax_sh[w * 8 + ((lane >> 2) & 7)] = dx;
        __syncthreads();                                   // B1

        // ---- softmax over S=64 (redundant in every warp) + z partial ----
        float4 z = make_float4(0.f, 0.f, 0.f, 0.f);
        {
            float a = ax_sh[lane];
            float b = ax_sh[lane + 32];
            float m = fmaxf(a, b);
            #pragma unroll
            for (int o = 16; o; o >>= 1) m = fmaxf(m, __shfl_xor_sync(0xffffffffu, m, o));
            float ea = __expf(a - m), eb = __expf(b - m);
            float s = ea + eb;
            #pragma unroll
            for (int o = 16; o; o >>= 1) s += __shfl_xor_sync(0xffffffffu, s, o);
            float inv = __fdividef(1.f, s);
            float sel  = (w & 4) ? eb : ea;
            int   base = (w & 3) * 8;
            #pragma unroll
            for (int i = 0; i < 8; ++i) {
                float av = __shfl_sync(0xffffffffu, sel, base + i) * inv;
                z.x = fmaf(av, ev[i].x, z.x);
                z.y = fmaf(av, ev[i].y, z.y);
                z.z = fmaf(av, ev[i].z, z.z);
                z.w = fmaf(av, ev[i].w, z.w);
            }
        }

        // ---- ev[] now dead: ISSUE NEXT REVIEW'S GATHERS (latency hides
        //      under the whole aspect tail below) ----
        #pragma unroll
        for (int i = 0; i < 8; ++i) {
            int id = __shfl_sync(0xffffffffu, tokreg_n, i);
            ev[i] = reinterpret_cast<const float4*>(wemb + (size_t)id * DD)[lane];
        }

        reinterpret_cast<float4*>(red)[w * 32 + lane] = z;
        __syncthreads();                                   // B2

        // ---- z[d]: cross-warp sum of 8 partials ----
        if (t < DD) {
            float s = 0.f;
            #pragma unroll
            for (int w2 = 0; w2 < 8; ++w2)
                s += red[w2 * DD + t];
            z_sh[t] = s;
        }
        __syncthreads();                                   // B3

        // ---- aspect logits: thread (part, lane=k) -> 16-d partial ----
        {
            float a = 0.f;
            const float* zp = z_sh + part * 16;
            #pragma unroll
            for (int j = 0; j < 16; ++j)
                a = fmaf(zp[j], wwrow[j], a);
            lpart[part * KK + lane] = a;
        }
        __syncthreads();                                   // B4

        // ---- K-softmax: warp 0 only -> p_sh (others proceed to barrier) ----
        if (w == 0) {
            float a = wb_sh[lane];
            #pragma unroll
            for (int pp = 0; pp < 8; ++pp) a += lpart[pp * KK + lane];
            float m = a;
            #pragma unroll
            for (int o = 16; o; o >>= 1) m = fmaxf(m, __shfl_xor_sync(0xffffffffu, m, o));
            float e = __expf(a - m);
            float s = e;
            #pragma unroll
            for (int o = 16; o; o >>= 1) s += __shfl_xor_sync(0xffffffffu, s, o);
            p_sh[lane] = e * __fdividef(1.f, s);
        }
        __syncthreads();                                   // B5

        // ---- r_s[d] = Tb[d] + sum_k p[k] * Tw[k][d] (p via LDS broadcast) ----
        if (t < DD) {
            float a = tb_reg;
            #pragma unroll
            for (int k = 0; k < KK; ++k)
                a = fmaf(p_sh[k], twS[k * DD + t], a);
            g_rs[(size_t)r * DD + t] = a;
        }

        // ---- stage next v into SMEM; rotate token regs ----
        if (t < DD) v_sh[t] = v_pf_n;
        tokreg = tokreg_n;
        __syncthreads();   // B6: protects ax_sh/red/lpart/p_sh/v_sh for next iter
    }
}

// ================= kernel 3: fused segment-mean + prediction =================
__global__ void __launch_bounds__(256) final_kernel(
    const int*   __restrict__ user, const int* __restrict__ item,
    const int*   __restrict__ uidx, const int* __restrict__ iidx,
    const float* __restrict__ uemb, const float* __restrict__ iemb,
    const float* __restrict__ avg,  float* __restrict__ out)
{
    __shared__ float sh[256];
    __shared__ float red[4];

    const int b    = blockIdx.x;
    const int t    = threadIdx.x;
    const int side = t >> 7;          // 0 = user, 1 = item
    const int d    = t & 127;

    float uf = 0.f, itf = 0.f;
    if (t < DD) {
        uf  = uemb[(size_t)user[b] * DD + t];
        itf = iemb[(size_t)item[b] * DD + t];
    }

    const int* idxp = side ? iidx : uidx;
    const int  base = b * PER;

    int ids[PER];
    #pragma unroll
    for (int j = 0; j < PER; ++j)
        ids[j] = __ldg(idxp + base + j);      // PER independent LDG

    float sum = 0.f;
    #pragma unroll
    for (int j = 0; j < PER; ++j)
        sum += g_rs[(size_t)ids[j] * DD + d]; // PER independent LDG

    sh[t] = sum * (1.0f / (float)PER);
    __syncthreads();

    if (t < DD) {
        float p = sh[t] * sh[t + 128] + uf * itf;
        #pragma unroll
        for (int o = 16; o; o >>= 1) p += __shfl_xor_sync(0xffffffffu, p, o);
        if ((t & 31) == 0) red[t >> 5] = p;
    }
    __syncthreads();
    if (t == 0) out[b] = red[0] + red[1] + red[2] + red[3] + avg[0];
}

// ---------------- launch ----------------
extern "C" void kernel_launch(void* const* d_in, const int* in_sizes, int n_in,
                              void* d_out, int out_size)
{
    const int*   user = (const int*)  d_in[0];
    const int*   item = (const int*)  d_in[1];
    const int*   hrev = (const int*)  d_in[2];
    const float* ypos = (const float*)d_in[3];
    const int*   uidx = (const int*)  d_in[4];
    const int*   iidx = (const int*)  d_in[6];
    const float* wemb = (const float*)d_in[8];
    const float* Mw   = (const float*)d_in[9];
    // d_in[10] = M_b: constant shift over s -> cancels in softmax, unused
    const float* Ww   = (const float*)d_in[11];
    const float* Wb   = (const float*)d_in[12];
    const float* Tw   = (const float*)d_in[13];
    const float* Tb   = (const float*)d_in[14];
    const float* uemb = (const float*)d_in[15];
    const float* iemb = (const float*)d_in[16];
    const float* avg  = (const float*)d_in[17];
    float* out = (float*)d_out;

    vprep_kernel <<<(RR + 63) / 64, 256>>>(Mw, ypos);   // 313 blocks x 64 reviews
    review_kernel<<<GRID_REVIEW, 256>>>(hrev, wemb, Ww, Wb, Tw, Tb);
    final_kernel <<<BB, 256>>>(user, item, uidx, iidx, uemb, iemb, avg, out);
}